// round 2
// baseline (speedup 1.0000x reference)
#include <cuda_runtime.h>
#include <cuda_bf16.h>
#include <cstdint>

// ---------------------------------------------------------------------------
// Problem constants
// ---------------------------------------------------------------------------
#define NLAY 2
#define HEADS 4
#define CDIM 512
#define INDIM 256
#define FAN 16
#define NSEED 256
#define NCLS 47
#define DHEAD 128
#define N0 256
#define N1 4096
#define N2 65536

// ---------------------------------------------------------------------------
// Scratch (static device globals; no runtime allocation)
// ---------------------------------------------------------------------------
__device__ float g_st0[N0 * CDIM];
__device__ float g_st1[N1 * CDIM];
__device__ float g_aggf2[N1 * INDIM];
__device__ float g_cs1[N1];
__device__ float g_dn1[N1];
__device__ float g_aggA[N1 * CDIM];   // depth-1 aggregation
__device__ float g_aggB[N0 * CDIM];   // depth-0 aggregation
__device__ float g_hl[N1 * CDIM];     // scratch (sage out / proj out)
__device__ float g_h[N1 * CDIM];      // post-LN1
__device__ float g_h2[N1 * CDIM];     // post-LN2
__device__ float g_qkv[N1 * 3 * CDIM];
__device__ float g_attn[N1 * CDIM];
__device__ float g_f1[N1 * 2 * CDIM];
__device__ float g_scores[(size_t)N1 * N1];  // 67 MB, reused per head

// ---------------------------------------------------------------------------
// Generic SGEMM  C[M,N] = alpha * A[M,K] @ W[N,K]^T   (NT: both K-contiguous)
// epilogue: (+bias[n]) (relu) (+res[m,n]) (*rowscale[m]) (accumulate)
// ---------------------------------------------------------------------------
#define GF_RELU  1
#define GF_ACCUM 2

__global__ void __launch_bounds__(256, 2) gemm_nt(
    const float* __restrict__ A, int lda,
    const float* __restrict__ W, int ldw,
    float* __restrict__ C, int ldc,
    int M, int N, int K,
    const float* __restrict__ bias,
    const float* __restrict__ res, int ldres,
    const float* __restrict__ rowscale,
    float alpha, int flags)
{
    __shared__ float As[8][132];
    __shared__ float Ws[8][132];

    const int tid = threadIdx.x;
    const int bm = blockIdx.y * 128, bn = blockIdx.x * 128;
    const int tx = tid & 15, ty = tid >> 4;
    const int lr = tid >> 1;        // 0..127
    const int lk = (tid & 1) * 4;   // 0 or 4

    float acc[8][8];
#pragma unroll
    for (int i = 0; i < 8; i++)
#pragma unroll
        for (int j = 0; j < 8; j++) acc[i][j] = 0.f;

    for (int k0 = 0; k0 < K; k0 += 8) {
        float4 va = make_float4(0.f, 0.f, 0.f, 0.f);
        float4 vw = make_float4(0.f, 0.f, 0.f, 0.f);
        const int ar = bm + lr;
        if (ar < M && (k0 + lk + 3) < K)
            va = *(const float4*)(A + (size_t)ar * lda + k0 + lk);
        const int wr = bn + lr;
        if (wr < N && (k0 + lk + 3) < K)
            vw = *(const float4*)(W + (size_t)wr * ldw + k0 + lk);
        As[lk + 0][lr] = va.x; As[lk + 1][lr] = va.y;
        As[lk + 2][lr] = va.z; As[lk + 3][lr] = va.w;
        Ws[lk + 0][lr] = vw.x; Ws[lk + 1][lr] = vw.y;
        Ws[lk + 2][lr] = vw.z; Ws[lk + 3][lr] = vw.w;
        __syncthreads();
#pragma unroll
        for (int k = 0; k < 8; k++) {
            float ra[8], rb[8];
#pragma unroll
            for (int i = 0; i < 8; i++) ra[i] = As[k][ty * 8 + i];
#pragma unroll
            for (int j = 0; j < 8; j++) rb[j] = Ws[k][tx * 8 + j];
#pragma unroll
            for (int i = 0; i < 8; i++)
#pragma unroll
                for (int j = 0; j < 8; j++)
                    acc[i][j] += ra[i] * rb[j];
        }
        __syncthreads();
    }

#pragma unroll
    for (int i = 0; i < 8; i++) {
        const int gm = bm + ty * 8 + i;
        if (gm >= M) continue;
        const float rsc = rowscale ? rowscale[gm] : 1.f;
#pragma unroll
        for (int j = 0; j < 8; j++) {
            const int gn = bn + tx * 8 + j;
            if (gn >= N) continue;
            float v = acc[i][j] * alpha;
            if (bias) v += bias[gn];
            if (flags & GF_RELU) v = fmaxf(v, 0.f);
            if (res) v += res[(size_t)gm * ldres + gn];
            if (rowscale) v *= rsc;
            float* cp = C + (size_t)gm * ldc + gn;
            if (flags & GF_ACCUM) *cp += v; else *cp = v;
        }
    }
}

// ---------------------------------------------------------------------------
// SGEMM NN: C[M,N] = A[M,K] @ B[K,N]   (attention AV)
// ---------------------------------------------------------------------------
__global__ void __launch_bounds__(256, 2) gemm_nn(
    const float* __restrict__ A, int lda,
    const float* __restrict__ B, int ldb,
    float* __restrict__ C, int ldc,
    int M, int N, int K)
{
    __shared__ float As[8][132];
    __shared__ float Bs[8][132];

    const int tid = threadIdx.x;
    const int bm = blockIdx.y * 128, bn = blockIdx.x * 128;
    const int tx = tid & 15, ty = tid >> 4;
    const int lr = tid >> 1;
    const int lk = (tid & 1) * 4;
    const int brow = tid >> 5;           // 0..7
    const int bcol = (tid & 31) * 4;     // 0..124

    float acc[8][8];
#pragma unroll
    for (int i = 0; i < 8; i++)
#pragma unroll
        for (int j = 0; j < 8; j++) acc[i][j] = 0.f;

    for (int k0 = 0; k0 < K; k0 += 8) {
        float4 va = make_float4(0.f, 0.f, 0.f, 0.f);
        float4 vb = make_float4(0.f, 0.f, 0.f, 0.f);
        const int ar = bm + lr;
        if (ar < M && (k0 + lk + 3) < K)
            va = *(const float4*)(A + (size_t)ar * lda + k0 + lk);
        if ((k0 + brow) < K && (bn + bcol + 3) < N)
            vb = *(const float4*)(B + (size_t)(k0 + brow) * ldb + bn + bcol);
        As[lk + 0][lr] = va.x; As[lk + 1][lr] = va.y;
        As[lk + 2][lr] = va.z; As[lk + 3][lr] = va.w;
        *(float4*)&Bs[brow][bcol] = vb;
        __syncthreads();
#pragma unroll
        for (int k = 0; k < 8; k++) {
            float ra[8], rb[8];
#pragma unroll
            for (int i = 0; i < 8; i++) ra[i] = As[k][ty * 8 + i];
#pragma unroll
            for (int j = 0; j < 8; j++) rb[j] = Bs[k][tx * 8 + j];
#pragma unroll
            for (int i = 0; i < 8; i++)
#pragma unroll
                for (int j = 0; j < 8; j++)
                    acc[i][j] += ra[i] * rb[j];
        }
        __syncthreads();
    }

#pragma unroll
    for (int i = 0; i < 8; i++) {
        const int gm = bm + ty * 8 + i;
        if (gm >= M) continue;
#pragma unroll
        for (int j = 0; j < 8; j++) {
            const int gn = bn + tx * 8 + j;
            if (gn >= N) continue;
            C[(size_t)gm * ldc + gn] = acc[i][j];
        }
    }
}

// ---------------------------------------------------------------------------
// Pre-aggregate raw feats2 with nbmask1*nmask2 weights (folds the 65536-row
// embedding away).  aggf[i,c] = sum_f w_f * feats2[i*F+f, c]
// cs[i] = sum_f w_f ;  dn[i] = max(sum_f nb_f, 1)
// ---------------------------------------------------------------------------
__global__ void preagg2_kernel(const float* __restrict__ feats2,
                               const float* __restrict__ nmask2,
                               const int* __restrict__ nbm1,
                               float* __restrict__ aggf,
                               float* __restrict__ cs,
                               float* __restrict__ dn)
{
    const int i = blockIdx.x;
    const int tid = threadIdx.x;  // 256
    __shared__ float w[FAN];
    if (tid < FAN) {
        const int nb = nbm1[i * FAN + tid];
        w[tid] = nb ? nmask2[i * FAN + tid] : 0.f;
    }
    __syncthreads();
    if (tid == 0) {
        float s = 0.f, d = 0.f;
        for (int f = 0; f < FAN; f++) {
            s += w[f];
            d += (float)nbm1[i * FAN + f];
        }
        cs[i] = s;
        dn[i] = fmaxf(d, 1.f);
    }
    float s = 0.f;
    const int c = tid;  // INDIM == 256 == blockDim
#pragma unroll
    for (int f = 0; f < FAN; f++)
        s += w[f] * feats2[((size_t)i * FAN + f) * INDIM + c];
    aggf[(size_t)i * INDIM + c] = s;
}

// agg = (gemm_out + emb_b * cs) / dn   (row-wise)
__global__ void finalize_agg1(float* __restrict__ agg,
                              const float* __restrict__ emb_b,
                              const float* __restrict__ cs,
                              const float* __restrict__ dn)
{
    const int i = blockIdx.x;
    const int c = threadIdx.x;  // 512
    const size_t o = (size_t)i * CDIM + c;
    agg[o] = (agg[o] + emb_b[c] * cs[i]) / dn[i];
}

// masked mean over F children of a state matrix (children already node-masked)
__global__ void agg_mean(const float* __restrict__ child,
                         const int* __restrict__ nbm,
                         float* __restrict__ out)
{
    const int i = blockIdx.x;
    const int tid = threadIdx.x;  // 256
    __shared__ float w[FAN];
    __shared__ float dninv;
    if (tid < FAN) w[tid] = (float)nbm[i * FAN + tid];
    __syncthreads();
    if (tid == 0) {
        float s = 0.f;
        for (int f = 0; f < FAN; f++) s += w[f];
        dninv = 1.f / fmaxf(s, 1.f);
    }
    __syncthreads();
    for (int c = tid; c < CDIM; c += 256) {
        float s = 0.f;
#pragma unroll
        for (int f = 0; f < FAN; f++)
            s += w[f] * child[((size_t)i * FAN + f) * CDIM + c];
        out[(size_t)i * CDIM + c] = s * dninv;
    }
}

// out = LayerNorm(a + b) * g + beta  (row length 512, 256 threads/row)
__global__ void ln_res(const float* __restrict__ a,
                       const float* __restrict__ b,
                       const float* __restrict__ g,
                       const float* __restrict__ be,
                       float* __restrict__ out)
{
    const int row = blockIdx.x;
    const int tid = threadIdx.x;  // 256
    const float* ar = a + (size_t)row * CDIM;
    const float* br = b + (size_t)row * CDIM;
    const float x0 = ar[tid] + br[tid];
    const float x1 = ar[tid + 256] + br[tid + 256];
    float s = x0 + x1;
    float ss = x0 * x0 + x1 * x1;
    __shared__ float rs[8], rss[8];
#pragma unroll
    for (int o = 16; o > 0; o >>= 1) {
        s += __shfl_down_sync(0xffffffffu, s, o);
        ss += __shfl_down_sync(0xffffffffu, ss, o);
    }
    if ((tid & 31) == 0) { rs[tid >> 5] = s; rss[tid >> 5] = ss; }
    __syncthreads();
    if (tid == 0) {
        float S = 0.f, SS = 0.f;
        for (int i = 0; i < 8; i++) { S += rs[i]; SS += rss[i]; }
        const float mu = S * (1.f / CDIM);
        rs[0] = mu;
        rss[0] = rsqrtf(SS * (1.f / CDIM) - mu * mu + 1e-5f);
    }
    __syncthreads();
    const float mu = rs[0], inv = rss[0];
    out[(size_t)row * CDIM + tid]       = (x0 - mu) * inv * g[tid] + be[tid];
    out[(size_t)row * CDIM + tid + 256] = (x1 - mu) * inv * g[tid + 256] + be[tid + 256];
}

// in-place row softmax over S[row][0..n)
__global__ void softmax_rows(float* __restrict__ S, int n)
{
    const int row = blockIdx.x;
    float* r = S + (size_t)row * n;
    const int tid = threadIdx.x;  // 256
    __shared__ float red[8];

    float m = -1e30f;
    for (int j = tid; j < n; j += 256) m = fmaxf(m, r[j]);
#pragma unroll
    for (int o = 16; o > 0; o >>= 1) m = fmaxf(m, __shfl_xor_sync(0xffffffffu, m, o));
    if ((tid & 31) == 0) red[tid >> 5] = m;
    __syncthreads();
    if (tid < 8) {
        float v = red[tid];
#pragma unroll
        for (int o = 4; o > 0; o >>= 1) v = fmaxf(v, __shfl_xor_sync(0xffu, v, o));
        if (tid == 0) red[0] = v;
    }
    __syncthreads();
    m = red[0];
    __syncthreads();

    float s = 0.f;
    for (int j = tid; j < n; j += 256) {
        const float e = __expf(r[j] - m);
        r[j] = e;
        s += e;
    }
#pragma unroll
    for (int o = 16; o > 0; o >>= 1) s += __shfl_xor_sync(0xffffffffu, s, o);
    if ((tid & 31) == 0) red[tid >> 5] = s;
    __syncthreads();
    if (tid < 8) {
        float v = red[tid];
#pragma unroll
        for (int o = 4; o > 0; o >>= 1) v += __shfl_xor_sync(0xffu, v, o);
        if (tid == 0) red[0] = v;
    }
    __syncthreads();
    const float inv = 1.f / red[0];
    for (int j = tid; j < n; j += 256) r[j] *= inv;
}

// ---------------------------------------------------------------------------
// Host orchestration
// ---------------------------------------------------------------------------
static inline void launch_nt(const float* A, int lda,
                             const float* W, int ldw,
                             float* C, int ldc,
                             int M, int N, int K,
                             const float* bias, const float* res, int ldres,
                             const float* rowscale, float alpha, int flags)
{
    dim3 grid((N + 127) / 128, (M + 127) / 128, 1);
    gemm_nt<<<grid, 256>>>(A, lda, W, ldw, C, ldc,
                           M, N, K, bias, res, ldres, rowscale, alpha, flags);
}

extern "C" void kernel_launch(void* const* d_in, const int* in_sizes, int n_in,
                              void* d_out, int out_size)
{
    const float* feats0 = (const float*)d_in[0];
    const float* feats1 = (const float*)d_in[1];
    const float* feats2 = (const float*)d_in[2];
    const float* nmask0 = (const float*)d_in[3];
    const float* nmask1 = (const float*)d_in[4];
    const float* nmask2 = (const float*)d_in[5];
    const int*   nbm0   = (const int*)d_in[6];
    const int*   nbm1   = (const int*)d_in[7];
    const float* emb_w  = (const float*)d_in[8];
    const float* emb_b  = (const float*)d_in[9];
    const float* sage_w = (const float*)d_in[10];
    const float* sage_b = (const float*)d_in[11];
    const float* qkv_w  = (const float*)d_in[12];
    const float* qkv_b  = (const float*)d_in[13];
    const float* out_w  = (const float*)d_in[14];
    const float* out_b  = (const float*)d_in[15];
    const float* n1_g   = (const float*)d_in[16];
    const float* n1_b   = (const float*)d_in[17];
    const float* n2_g   = (const float*)d_in[18];
    const float* n2_b   = (const float*)d_in[19];
    const float* ffn_w1 = (const float*)d_in[20];
    const float* ffn_b1 = (const float*)d_in[21];
    const float* ffn_w2 = (const float*)d_in[22];
    const float* ffn_b2 = (const float*)d_in[23];
    const float* cls_w  = (const float*)d_in[24];
    const float* cls_b  = (const float*)d_in[25];

    float *st0, *st1, *aggf2, *cs1, *dn1, *aggA, *aggB;
    float *hl, *h, *h2, *qkv, *attn, *f1, *scores;
    cudaGetSymbolAddress((void**)&st0, g_st0);
    cudaGetSymbolAddress((void**)&st1, g_st1);
    cudaGetSymbolAddress((void**)&aggf2, g_aggf2);
    cudaGetSymbolAddress((void**)&cs1, g_cs1);
    cudaGetSymbolAddress((void**)&dn1, g_dn1);
    cudaGetSymbolAddress((void**)&aggA, g_aggA);
    cudaGetSymbolAddress((void**)&aggB, g_aggB);
    cudaGetSymbolAddress((void**)&hl, g_hl);
    cudaGetSymbolAddress((void**)&h, g_h);
    cudaGetSymbolAddress((void**)&h2, g_h2);
    cudaGetSymbolAddress((void**)&qkv, g_qkv);
    cudaGetSymbolAddress((void**)&attn, g_attn);
    cudaGetSymbolAddress((void**)&f1, g_f1);
    cudaGetSymbolAddress((void**)&scores, g_scores);

    const float ascale = 0.08838834764831845f;  // 1/sqrt(128)

    // --- folded depth-2 embedding: pre-aggregate raw feats2 ---
    preagg2_kernel<<<N1, 256>>>(feats2, nmask2, nbm1, aggf2, cs1, dn1);

    // --- depth-0/1 embeddings: st = (feats @ emb_w^T + emb_b) * nmask ---
    launch_nt(feats0, INDIM, emb_w, INDIM, st0, CDIM,
              N0, CDIM, INDIM, emb_b, nullptr, 0, nmask0, 1.f, 0);
    launch_nt(feats1, INDIM, emb_w, INDIM, st1, CDIM,
              N1, CDIM, INDIM, emb_b, nullptr, 0, nmask1, 1.f, 0);

    // one transformer-block application at (layer li) with n nodes
    auto process = [&](int li, int n, const float* sf, const float* agg,
                       const float* nmask, float* st_out) {
        const float* W1 = sage_w + (size_t)li * CDIM * 2 * CDIM;        // [512,1024]
        // h_local = sf@W1a^T + agg@W1b^T + sage_b
        launch_nt(sf, CDIM, W1, 2 * CDIM, hl, CDIM,
                  n, CDIM, CDIM, nullptr, nullptr, 0, nullptr, 1.f, 0);
        launch_nt(agg, CDIM, W1 + CDIM, 2 * CDIM, hl, CDIM,
                  n, CDIM, CDIM, sage_b + li * CDIM, nullptr, 0, nullptr,
                  1.f, GF_ACCUM);
        // h = LN(sf + h_local)
        ln_res<<<n, 256>>>(sf, hl, n1_g + li * CDIM, n1_b + li * CDIM, h);
        // qkv
        launch_nt(h, CDIM, qkv_w + (size_t)li * 3 * CDIM * CDIM, CDIM,
                  qkv, 3 * CDIM, n, 3 * CDIM, CDIM,
                  qkv_b + li * 3 * CDIM, nullptr, 0, nullptr, 1.f, 0);
        // attention, one head at a time (reuse scores buffer)
        for (int hh = 0; hh < HEADS; hh++) {
            // scores = (Q_h @ K_h^T) / sqrt(DH)
            launch_nt(qkv + hh * DHEAD, 3 * CDIM,
                      qkv + CDIM + hh * DHEAD, 3 * CDIM,
                      scores, n, n, n, DHEAD,
                      nullptr, nullptr, 0, nullptr, ascale, 0);
            softmax_rows<<<n, 256>>>(scores, n);
            // attn[:, hh*DH : (hh+1)*DH] = S @ V_h
            dim3 grid((DHEAD + 127) / 128, (n + 127) / 128, 1);
            gemm_nn<<<grid, 256>>>(scores, n,
                                   qkv + 2 * CDIM + hh * DHEAD, 3 * CDIM,
                                   attn + hh * DHEAD, CDIM, n, DHEAD, n);
        }
        // y = attn @ out_w^T + out_b ; h2 = LN(h + y)
        launch_nt(attn, CDIM, out_w + (size_t)li * CDIM * CDIM, CDIM,
                  hl, CDIM, n, CDIM, CDIM,
                  out_b + li * CDIM, nullptr, 0, nullptr, 1.f, 0);
        ln_res<<<n, 256>>>(h, hl, n2_g + li * CDIM, n2_b + li * CDIM, h2);
        // ffn: f1 = relu(h2@w1^T + b1) ; st_out = (f1@w2^T + b2 + h2)*nmask
        launch_nt(h2, CDIM, ffn_w1 + (size_t)li * 2 * CDIM * CDIM, CDIM,
                  f1, 2 * CDIM, n, 2 * CDIM, CDIM,
                  ffn_b1 + li * 2 * CDIM, nullptr, 0, nullptr, 1.f, GF_RELU);
        launch_nt(f1, 2 * CDIM, ffn_w2 + (size_t)li * CDIM * 2 * CDIM,
                  2 * CDIM, st_out, CDIM, n, CDIM, 2 * CDIM,
                  ffn_b2 + li * CDIM, h2, CDIM, nmask, 1.f, 0);
    };

    // ---- layer 0: depths {1, 0} (aggregations read PRE-update states) ----
    // depth-1 agg via folded embedding of pre-aggregated feats2
    launch_nt(aggf2, INDIM, emb_w, INDIM, aggA, CDIM,
              N1, CDIM, INDIM, nullptr, nullptr, 0, nullptr, 1.f, 0);
    finalize_agg1<<<N1, CDIM>>>(aggA, emb_b, cs1, dn1);
    // depth-0 agg from pre-update st1 (must run before depth-1 overwrites st1)
    agg_mean<<<N0, 256>>>(st1, nbm0, aggB);
    process(0, N1, st1, aggA, nmask1, st1);
    process(0, N0, st0, aggB, nmask0, st0);

    // ---- layer 1: depth {0} ----
    agg_mean<<<N0, 256>>>(st1, nbm0, aggB);
    process(1, N0, st0, aggB, nmask0, st0);

    // ---- classifier: out = st0 @ cls_w^T + cls_b ----
    launch_nt(st0, CDIM, cls_w, CDIM, (float*)d_out, NCLS,
              N0, NCLS, CDIM, cls_b, nullptr, 0, nullptr, 1.f, 0);
}

// round 4
// speedup vs baseline: 2.3627x; 2.3627x over previous
#include <cuda_runtime.h>
#include <cuda_bf16.h>
#include <cstdint>

// ---------------------------------------------------------------------------
// Problem constants
// ---------------------------------------------------------------------------
#define NLAY 2
#define HEADS 4
#define CDIM 512
#define INDIM 256
#define FAN 16
#define NCLS 47
#define DHEAD 128
#define N0 256
#define N1 4096

// ---------------------------------------------------------------------------
// Scratch (static device globals; total ~160 MB — matches the only
// memory profile that has passed the harness so far)
// ---------------------------------------------------------------------------
__device__ float g_st0[N0 * CDIM];
__device__ float g_st1[N1 * CDIM];
__device__ float g_aggf2[N1 * INDIM];
__device__ float g_cs1[N1];
__device__ float g_dn1[N1];
__device__ float g_aggA[N1 * CDIM];
__device__ float g_aggB[N0 * CDIM];
__device__ float g_hl[N1 * CDIM];
__device__ float g_h[N1 * CDIM];
__device__ float g_h2[N1 * CDIM];
__device__ float g_qkv[N1 * 3 * CDIM];
__device__ float g_vt[N1 * CDIM];             // transposed V [512][n]
__device__ float g_attn[N1 * CDIM];
__device__ float g_f1[N1 * 2 * CDIM];
__device__ float g_scores[(size_t)N1 * N1];   // 67 MB, reused per head

#define GF_RELU  1
#define GF_ACCUM 2

// ---------------------------------------------------------------------------
// tf32 helpers
// ---------------------------------------------------------------------------
__device__ __forceinline__ void cp_async16(uint32_t dst, const void* src, int nbytes) {
    asm volatile("cp.async.cg.shared.global [%0], [%1], 16, %2;\n"
                 :: "r"(dst), "l"(src), "r"(nbytes));
}
__device__ __forceinline__ void cp_commit() {
    asm volatile("cp.async.commit_group;\n");
}
__device__ __forceinline__ void cp_wait1() {
    asm volatile("cp.async.wait_group 1;\n");
}
__device__ __forceinline__ void cp_wait0() {
    asm volatile("cp.async.wait_group 0;\n");
}
__device__ __forceinline__ void split_tf32(float v, uint32_t& big, uint32_t& sml) {
    uint32_t vb = __float_as_uint(v) & 0xffffe000u;
    big = vb;
    sml = __float_as_uint(v - __uint_as_float(vb));
}
__device__ __forceinline__ void mma_tf32(float c[4], const uint32_t a[4], const uint32_t b[2]) {
    asm volatile(
        "mma.sync.aligned.m16n8k8.row.col.f32.tf32.tf32.f32 "
        "{%0,%1,%2,%3}, {%4,%5,%6,%7}, {%8,%9}, {%0,%1,%2,%3};\n"
        : "+f"(c[0]), "+f"(c[1]), "+f"(c[2]), "+f"(c[3])
        : "r"(a[0]), "r"(a[1]), "r"(a[2]), "r"(a[3]), "r"(b[0]), "r"(b[1]));
}

// ---------------------------------------------------------------------------
// 3xTF32 NT GEMM:  C[M,N] = alpha * A[M,K] @ W[N,K]^T  (K contiguous on both)
// block tile 128(M) x 64(N), K-tile 16, 256 threads, cp.async double buffer.
// epilogue: *alpha, +bias[n], relu, +res[m,n], *rowscale[m], accumulate.
// Requires K % 16 == 0 and 16B-aligned row starts (all shapes here comply).
// ---------------------------------------------------------------------------
#define PITCH 20

__global__ void __launch_bounds__(256) gemm_tf32(
    const float* __restrict__ A, int lda,
    const float* __restrict__ W, int ldw,
    float* __restrict__ C, int ldc,
    int M, int N, int K,
    const float* __restrict__ bias,
    const float* __restrict__ res, int ldres,
    const float* __restrict__ rowscale,
    float alpha, int flags)
{
    __shared__ float As[2][128 * PITCH];
    __shared__ float Ws[2][64 * PITCH];

    const int tid = threadIdx.x;
    const int bm = blockIdx.y * 128, bn = blockIdx.x * 64;
    const int lane = tid & 31, wid = tid >> 5;
    const int wm = (wid & 3) * 32;    // warp M offset within block
    const int wn = (wid >> 2) * 32;   // warp N offset within block
    const int lg = lane >> 2;         // 0..7
    const int lt = lane & 3;          // 0..3

    float acc[2][4][4];
#pragma unroll
    for (int i = 0; i < 2; i++)
#pragma unroll
        for (int j = 0; j < 4; j++)
#pragma unroll
            for (int r = 0; r < 4; r++) acc[i][j][r] = 0.f;

    const int T = K >> 4;  // number of 16-wide k-tiles

    auto issue_tile = [&](int buf, int kt) {
        const int k0 = kt << 4;
        // A: 128 rows x 4 16B-segments = 512 chunks, 2 per thread
#pragma unroll
        for (int u = 0; u < 2; u++) {
            const int c = tid + u * 256;
            const int row = c >> 2, seg = c & 3;
            const int gr = bm + row;
            const float* src = (gr < M) ? (A + (size_t)gr * lda + k0 + seg * 4) : A;
            uint32_t dst = (uint32_t)__cvta_generic_to_shared(
                &As[buf][row * PITCH + seg * 4]);
            cp_async16(dst, src, (gr < M) ? 16 : 0);
        }
        // W: 64 rows x 4 segments = 256 chunks, 1 per thread
        {
            const int row = tid >> 2, seg = tid & 3;
            const int gr = bn + row;
            const float* src = (gr < N) ? (W + (size_t)gr * ldw + k0 + seg * 4) : W;
            uint32_t dst = (uint32_t)__cvta_generic_to_shared(
                &Ws[buf][row * PITCH + seg * 4]);
            cp_async16(dst, src, (gr < N) ? 16 : 0);
        }
        cp_commit();
    };

    issue_tile(0, 0);
    int buf = 0;
    for (int kt = 0; kt < T; kt++) {
        const bool more = (kt + 1 < T);
        if (more) issue_tile(buf ^ 1, kt + 1);
        if (more) cp_wait1(); else cp_wait0();
        __syncthreads();

#pragma unroll
        for (int ks = 0; ks < 2; ks++) {
            const int k0 = ks * 8;
            uint32_t ab[2][4], asm_[2][4];
#pragma unroll
            for (int i = 0; i < 2; i++) {
                const int r = wm + i * 16 + lg;
                float v0 = As[buf][r * PITCH + k0 + lt];
                float v1 = As[buf][(r + 8) * PITCH + k0 + lt];
                float v2 = As[buf][r * PITCH + k0 + lt + 4];
                float v3 = As[buf][(r + 8) * PITCH + k0 + lt + 4];
                split_tf32(v0, ab[i][0], asm_[i][0]);
                split_tf32(v1, ab[i][1], asm_[i][1]);
                split_tf32(v2, ab[i][2], asm_[i][2]);
                split_tf32(v3, ab[i][3], asm_[i][3]);
            }
            uint32_t bb[4][2], bs[4][2];
#pragma unroll
            for (int j = 0; j < 4; j++) {
                const int r = wn + j * 8 + lg;
                float v0 = Ws[buf][r * PITCH + k0 + lt];
                float v1 = Ws[buf][r * PITCH + k0 + lt + 4];
                split_tf32(v0, bb[j][0], bs[j][0]);
                split_tf32(v1, bb[j][1], bs[j][1]);
            }
#pragma unroll
            for (int i = 0; i < 2; i++)
#pragma unroll
                for (int j = 0; j < 4; j++) {
                    mma_tf32(acc[i][j], ab[i], bb[j]);
                    mma_tf32(acc[i][j], ab[i], bs[j]);
                    mma_tf32(acc[i][j], asm_[i], bb[j]);
                }
        }
        __syncthreads();
        buf ^= 1;
    }

    // epilogue
#pragma unroll
    for (int i = 0; i < 2; i++) {
#pragma unroll
        for (int j = 0; j < 4; j++) {
#pragma unroll
            for (int rr = 0; rr < 2; rr++) {
                const int gm = bm + wm + i * 16 + lg + rr * 8;
                if (gm >= M) continue;
                const float rsc = rowscale ? rowscale[gm] : 1.f;
#pragma unroll
                for (int cc = 0; cc < 2; cc++) {
                    const int gn = bn + wn + j * 8 + lt * 2 + cc;
                    if (gn >= N) continue;
                    float v = acc[i][j][rr * 2 + cc] * alpha;
                    if (bias) v += bias[gn];
                    if (flags & GF_RELU) v = fmaxf(v, 0.f);
                    if (res) v += res[(size_t)gm * ldres + gn];
                    if (rowscale) v *= rsc;
                    float* cp = C + (size_t)gm * ldc + gn;
                    if (flags & GF_ACCUM) *cp += v; else *cp = v;
                }
            }
        }
    }
}

// ---------------------------------------------------------------------------
// V transpose: vt[ch][token] = qkv[token*1536 + 1024 + ch]   (ch 0..511)
// ---------------------------------------------------------------------------
__global__ void transpose_v(const float* __restrict__ qkv,
                            float* __restrict__ vt, int n)
{
    __shared__ float t[32][33];
    const int bx = blockIdx.x * 32;  // token base
    const int by = blockIdx.y * 32;  // channel base
    const int x = threadIdx.x, y = threadIdx.y;  // 32 x 8
#pragma unroll
    for (int r = y; r < 32; r += 8)
        t[r][x] = qkv[(size_t)(bx + r) * (3 * CDIM) + CDIM * 2 + by + x];
    __syncthreads();
#pragma unroll
    for (int r = y; r < 32; r += 8)
        vt[(size_t)(by + r) * n + bx + x] = t[x][r];
}

// ---------------------------------------------------------------------------
// Pre-aggregate raw feats2 (folds the 65536-row embedding away)
// ---------------------------------------------------------------------------
__global__ void preagg2_kernel(const float* __restrict__ feats2,
                               const float* __restrict__ nmask2,
                               const int* __restrict__ nbm1,
                               float* __restrict__ aggf,
                               float* __restrict__ cs,
                               float* __restrict__ dn)
{
    const int i = blockIdx.x;
    const int tid = threadIdx.x;  // 256
    __shared__ float w[FAN];
    if (tid < FAN) {
        const int nb = nbm1[i * FAN + tid];
        w[tid] = nb ? nmask2[i * FAN + tid] : 0.f;
    }
    __syncthreads();
    if (tid == 0) {
        float s = 0.f, d = 0.f;
        for (int f = 0; f < FAN; f++) {
            s += w[f];
            d += (float)nbm1[i * FAN + f];
        }
        cs[i] = s;
        dn[i] = fmaxf(d, 1.f);
    }
    float s = 0.f;
    const int c = tid;
#pragma unroll
    for (int f = 0; f < FAN; f++)
        s += w[f] * feats2[((size_t)i * FAN + f) * INDIM + c];
    aggf[(size_t)i * INDIM + c] = s;
}

__global__ void finalize_agg1(float* __restrict__ agg,
                              const float* __restrict__ emb_b,
                              const float* __restrict__ cs,
                              const float* __restrict__ dn)
{
    const int i = blockIdx.x;
    const int c = threadIdx.x;  // 512
    const size_t o = (size_t)i * CDIM + c;
    agg[o] = (agg[o] + emb_b[c] * cs[i]) / dn[i];
}

__global__ void agg_mean(const float* __restrict__ child,
                         const int* __restrict__ nbm,
                         float* __restrict__ out)
{
    const int i = blockIdx.x;
    const int tid = threadIdx.x;  // 256
    __shared__ float w[FAN];
    __shared__ float dninv;
    if (tid < FAN) w[tid] = (float)nbm[i * FAN + tid];
    __syncthreads();
    if (tid == 0) {
        float s = 0.f;
        for (int f = 0; f < FAN; f++) s += w[f];
        dninv = 1.f / fmaxf(s, 1.f);
    }
    __syncthreads();
    for (int c = tid; c < CDIM; c += 256) {
        float s = 0.f;
#pragma unroll
        for (int f = 0; f < FAN; f++)
            s += w[f] * child[((size_t)i * FAN + f) * CDIM + c];
        out[(size_t)i * CDIM + c] = s * dninv;
    }
}

__global__ void ln_res(const float* __restrict__ a,
                       const float* __restrict__ b,
                       const float* __restrict__ g,
                       const float* __restrict__ be,
                       float* __restrict__ out)
{
    const int row = blockIdx.x;
    const int tid = threadIdx.x;  // 256
    const float* ar = a + (size_t)row * CDIM;
    const float* br = b + (size_t)row * CDIM;
    const float x0 = ar[tid] + br[tid];
    const float x1 = ar[tid + 256] + br[tid + 256];
    float s = x0 + x1;
    float ss = x0 * x0 + x1 * x1;
    __shared__ float rs[8], rss[8];
#pragma unroll
    for (int o = 16; o > 0; o >>= 1) {
        s += __shfl_down_sync(0xffffffffu, s, o);
        ss += __shfl_down_sync(0xffffffffu, ss, o);
    }
    if ((tid & 31) == 0) { rs[tid >> 5] = s; rss[tid >> 5] = ss; }
    __syncthreads();
    if (tid == 0) {
        float S = 0.f, SS = 0.f;
        for (int i = 0; i < 8; i++) { S += rs[i]; SS += rss[i]; }
        const float mu = S * (1.f / CDIM);
        rs[0] = mu;
        rss[0] = rsqrtf(SS * (1.f / CDIM) - mu * mu + 1e-5f);
    }
    __syncthreads();
    const float mu = rs[0], inv = rss[0];
    out[(size_t)row * CDIM + tid]       = (x0 - mu) * inv * g[tid] + be[tid];
    out[(size_t)row * CDIM + tid + 256] = (x1 - mu) * inv * g[tid + 256] + be[tid + 256];
}

// in-place row softmax over S[row][0..n)
__global__ void softmax_rows(float* __restrict__ S, int n)
{
    const int row = blockIdx.x;
    float* r = S + (size_t)row * n;
    const int tid = threadIdx.x;  // 256
    __shared__ float red[8];

    float m = -1e30f;
    for (int j = tid; j < n; j += 256) m = fmaxf(m, r[j]);
#pragma unroll
    for (int o = 16; o > 0; o >>= 1) m = fmaxf(m, __shfl_xor_sync(0xffffffffu, m, o));
    if ((tid & 31) == 0) red[tid >> 5] = m;
    __syncthreads();
    if (tid < 8) {
        float v = red[tid];
#pragma unroll
        for (int o = 4; o > 0; o >>= 1) v = fmaxf(v, __shfl_xor_sync(0xffu, v, o));
        if (tid == 0) red[0] = v;
    }
    __syncthreads();
    m = red[0];
    __syncthreads();

    float s = 0.f;
    for (int j = tid; j < n; j += 256) {
        const float e = __expf(r[j] - m);
        r[j] = e;
        s += e;
    }
#pragma unroll
    for (int o = 16; o > 0; o >>= 1) s += __shfl_xor_sync(0xffffffffu, s, o);
    if ((tid & 31) == 0) red[tid >> 5] = s;
    __syncthreads();
    if (tid < 8) {
        float v = red[tid];
#pragma unroll
        for (int o = 4; o > 0; o >>= 1) v += __shfl_xor_sync(0xffu, v, o);
        if (tid == 0) red[0] = v;
    }
    __syncthreads();
    const float inv = 1.f / red[0];
    for (int j = tid; j < n; j += 256) r[j] *= inv;
}

// ---------------------------------------------------------------------------
// Host orchestration
// ---------------------------------------------------------------------------
static inline void launch_g(const float* A, int lda,
                            const float* W, int ldw,
                            float* C, int ldc,
                            int M, int N, int K,
                            const float* bias, const float* res, int ldres,
                            const float* rowscale, float alpha, int flags)
{
    dim3 grid((N + 63) / 64, (M + 127) / 128, 1);
    gemm_tf32<<<grid, 256>>>(A, lda, W, ldw, C, ldc,
                             M, N, K, bias, res, ldres, rowscale, alpha, flags);
}

extern "C" void kernel_launch(void* const* d_in, const int* in_sizes, int n_in,
                              void* d_out, int out_size)
{
    const float* feats0 = (const float*)d_in[0];
    const float* feats1 = (const float*)d_in[1];
    const float* feats2 = (const float*)d_in[2];
    const float* nmask0 = (const float*)d_in[3];
    const float* nmask1 = (const float*)d_in[4];
    const float* nmask2 = (const float*)d_in[5];
    const int*   nbm0   = (const int*)d_in[6];
    const int*   nbm1   = (const int*)d_in[7];
    const float* emb_w  = (const float*)d_in[8];
    const float* emb_b  = (const float*)d_in[9];
    const float* sage_w = (const float*)d_in[10];
    const float* sage_b = (const float*)d_in[11];
    const float* qkv_w  = (const float*)d_in[12];
    const float* qkv_b  = (const float*)d_in[13];
    const float* out_w  = (const float*)d_in[14];
    const float* out_b  = (const float*)d_in[15];
    const float* n1_g   = (const float*)d_in[16];
    const float* n1_b   = (const float*)d_in[17];
    const float* n2_g   = (const float*)d_in[18];
    const float* n2_b   = (const float*)d_in[19];
    const float* ffn_w1 = (const float*)d_in[20];
    const float* ffn_b1 = (const float*)d_in[21];
    const float* ffn_w2 = (const float*)d_in[22];
    const float* ffn_b2 = (const float*)d_in[23];
    const float* cls_w  = (const float*)d_in[24];
    const float* cls_b  = (const float*)d_in[25];

    float *st0, *st1, *aggf2, *cs1, *dn1, *aggA, *aggB;
    float *hl, *h, *h2, *qkv, *vt, *attn, *f1, *scores;
    cudaGetSymbolAddress((void**)&st0, g_st0);
    cudaGetSymbolAddress((void**)&st1, g_st1);
    cudaGetSymbolAddress((void**)&aggf2, g_aggf2);
    cudaGetSymbolAddress((void**)&cs1, g_cs1);
    cudaGetSymbolAddress((void**)&dn1, g_dn1);
    cudaGetSymbolAddress((void**)&aggA, g_aggA);
    cudaGetSymbolAddress((void**)&aggB, g_aggB);
    cudaGetSymbolAddress((void**)&hl, g_hl);
    cudaGetSymbolAddress((void**)&h, g_h);
    cudaGetSymbolAddress((void**)&h2, g_h2);
    cudaGetSymbolAddress((void**)&qkv, g_qkv);
    cudaGetSymbolAddress((void**)&vt, g_vt);
    cudaGetSymbolAddress((void**)&attn, g_attn);
    cudaGetSymbolAddress((void**)&f1, g_f1);
    cudaGetSymbolAddress((void**)&scores, g_scores);

    const float ascale = 0.08838834764831845f;  // 1/sqrt(128)

    // --- folded depth-2 embedding: pre-aggregate raw feats2 ---
    preagg2_kernel<<<N1, 256>>>(feats2, nmask2, nbm1, aggf2, cs1, dn1);

    // --- depth-0/1 embeddings: st = (feats @ emb_w^T + emb_b) * nmask ---
    launch_g(feats0, INDIM, emb_w, INDIM, st0, CDIM,
             N0, CDIM, INDIM, emb_b, nullptr, 0, nmask0, 1.f, 0);
    launch_g(feats1, INDIM, emb_w, INDIM, st1, CDIM,
             N1, CDIM, INDIM, emb_b, nullptr, 0, nmask1, 1.f, 0);

    auto process = [&](int li, int n, const float* sf, const float* agg,
                       const float* nmask, float* st_out) {
        const float* W1 = sage_w + (size_t)li * CDIM * 2 * CDIM;
        // h_local = sf@W1a^T + agg@W1b^T + sage_b
        launch_g(sf, CDIM, W1, 2 * CDIM, hl, CDIM,
                 n, CDIM, CDIM, nullptr, nullptr, 0, nullptr, 1.f, 0);
        launch_g(agg, CDIM, W1 + CDIM, 2 * CDIM, hl, CDIM,
                 n, CDIM, CDIM, sage_b + li * CDIM, nullptr, 0, nullptr,
                 1.f, GF_ACCUM);
        ln_res<<<n, 256>>>(sf, hl, n1_g + li * CDIM, n1_b + li * CDIM, h);
        // qkv
        launch_g(h, CDIM, qkv_w + (size_t)li * 3 * CDIM * CDIM, CDIM,
                 qkv, 3 * CDIM, n, 3 * CDIM, CDIM,
                 qkv_b + li * 3 * CDIM, nullptr, 0, nullptr, 1.f, 0);
        // transpose V for NT AV-gemm
        transpose_v<<<dim3(n / 32, 16), dim3(32, 8)>>>(qkv, vt, n);
        // attention per head (single 67 MB scores buffer)
        for (int hh = 0; hh < HEADS; hh++) {
            launch_g(qkv + hh * DHEAD, 3 * CDIM,
                     qkv + CDIM + hh * DHEAD, 3 * CDIM,
                     scores, n, n, n, DHEAD,
                     nullptr, nullptr, 0, nullptr, ascale, 0);
            softmax_rows<<<n, 256>>>(scores, n);
            // attn[:, hh*DH:] = S @ V_hh   (NT with W = vt rows hh*DH..)
            launch_g(scores, n, vt + (size_t)hh * DHEAD * n, n,
                     attn + hh * DHEAD, CDIM, n, DHEAD, n,
                     nullptr, nullptr, 0, nullptr, 1.f, 0);
        }
        // y = attn @ out_w^T + out_b ; h2 = LN(h + y)
        launch_g(attn, CDIM, out_w + (size_t)li * CDIM * CDIM, CDIM,
                 hl, CDIM, n, CDIM, CDIM,
                 out_b + li * CDIM, nullptr, 0, nullptr, 1.f, 0);
        ln_res<<<n, 256>>>(h, hl, n2_g + li * CDIM, n2_b + li * CDIM, h2);
        // ffn
        launch_g(h2, CDIM, ffn_w1 + (size_t)li * 2 * CDIM * CDIM, CDIM,
                 f1, 2 * CDIM, n, 2 * CDIM, CDIM,
                 ffn_b1 + li * 2 * CDIM, nullptr, 0, nullptr, 1.f, GF_RELU);
        launch_g(f1, 2 * CDIM, ffn_w2 + (size_t)li * CDIM * 2 * CDIM,
                 2 * CDIM, st_out, CDIM, n, CDIM, 2 * CDIM,
                 ffn_b2 + li * CDIM, h2, CDIM, nmask, 1.f, 0);
    };

    // ---- layer 0: depths {1, 0} (aggregations read PRE-update states) ----
    launch_g(aggf2, INDIM, emb_w, INDIM, aggA, CDIM,
             N1, CDIM, INDIM, nullptr, nullptr, 0, nullptr, 1.f, 0);
    finalize_agg1<<<N1, CDIM>>>(aggA, emb_b, cs1, dn1);
    agg_mean<<<N0, 256>>>(st1, nbm0, aggB);  // before st1 is overwritten
    process(0, N1, st1, aggA, nmask1, st1);
    process(0, N0, st0, aggB, nmask0, st0);

    // ---- layer 1: depth {0} ----
    agg_mean<<<N0, 256>>>(st1, nbm0, aggB);
    process(1, N0, st0, aggB, nmask0, st0);

    // ---- classifier ----
    launch_g(st0, CDIM, cls_w, CDIM, (float*)d_out, NCLS,
             N0, NCLS, CDIM, cls_b, nullptr, 0, nullptr, 1.f, 0);
}